// round 3
// baseline (speedup 1.0000x reference)
#include <cuda_runtime.h>
#include <cuda_bf16.h>
#include <math.h>

// Problem constants
#define B_  2
#define S_  2048
#define D_  2048
#define H_  16
#define G_  4
#define DH_ 128
#define KV_ 512          // G_ * DH_
#define MS_ (B_ * S_)    // 4096 rows in the flattened GEMMs

// -------------------- scratch (device globals; no allocs allowed) ----------
__device__ float g_Q[MS_ * D_];    // [B*S, D]  = Q in [B,S,H,DH] layout
__device__ float g_K[MS_ * KV_];   // [B*S, KV] = K in [B,S,G,DH] layout
__device__ float g_V[MS_ * KV_];
__device__ float g_O[MS_ * D_];    // attention output, [B,S,H,DH] layout

// ======================= GEMM: C = A[M,K] @ W[K,N] + bias ==================
// 64x64 tile, BK=16, 256 threads, 4x4 micro-tile per thread.
#define BM 64
#define BN 64
#define BK 16

__global__ __launch_bounds__(256)
void gemm_bias_kernel(const float* __restrict__ A, const float* __restrict__ W,
                      const float* __restrict__ bias, float* __restrict__ C,
                      int M, int N, int K)
{
    __shared__ float As[BK][BM + 4];  // transposed: As[k][m]
    __shared__ float Bs[BK][BN];

    const int tid = threadIdx.x;
    const int tx = tid & 15;          // 0..15 -> N micro
    const int ty = tid >> 4;          // 0..15 -> M micro
    const int bm = blockIdx.y * BM;
    const int bn = blockIdx.x * BN;

    // A-tile loader: each thread one float4 of a 64x16 tile
    const int a_r = tid >> 2;               // 0..63
    const int a_c = (tid & 3) * 4;          // 0,4,8,12
    // B-tile loader: each thread one float4 of a 16x64 tile
    const int b_r = tid >> 4;               // 0..15
    const int b_c = (tid & 15) * 4;         // 0..60

    const float* Ap = A + (size_t)(bm + a_r) * K + a_c;
    const float* Bp = W + (size_t)b_r * N + bn + b_c;

    float acc[4][4];
#pragma unroll
    for (int i = 0; i < 4; i++)
#pragma unroll
        for (int j = 0; j < 4; j++) acc[i][j] = 0.0f;

    for (int k0 = 0; k0 < K; k0 += BK) {
        float4 av = *(const float4*)(Ap + k0);
        As[a_c + 0][a_r] = av.x;
        As[a_c + 1][a_r] = av.y;
        As[a_c + 2][a_r] = av.z;
        As[a_c + 3][a_r] = av.w;
        *(float4*)&Bs[b_r][b_c] = *(const float4*)(Bp + (size_t)k0 * N);
        __syncthreads();

#pragma unroll
        for (int k = 0; k < BK; k++) {
            float4 a4 = *(const float4*)&As[k][ty * 4];
            float4 b4 = *(const float4*)&Bs[k][tx * 4];
            float ar[4] = {a4.x, a4.y, a4.z, a4.w};
            float br[4] = {b4.x, b4.y, b4.z, b4.w};
#pragma unroll
            for (int i = 0; i < 4; i++)
#pragma unroll
                for (int j = 0; j < 4; j++)
                    acc[i][j] += ar[i] * br[j];
        }
        __syncthreads();
    }

#pragma unroll
    for (int i = 0; i < 4; i++) {
        int row = bm + ty * 4 + i;
#pragma unroll
        for (int j = 0; j < 4; j++) {
            int col = bn + tx * 4 + j;
            C[(size_t)row * N + col] = acc[i][j] + bias[col];
        }
    }
}

// ======================= Flash attention (fp32, causal, GQA) ===============
// Grid: (S/64, B*H). Block: 256 threads.
// Thread t: query row q = t/4 (0..63), quad lane l4 = t%4 owns dh slice l4*32..+31.
#define AM 64

__global__ __launch_bounds__(256)
void attn_kernel(const float* __restrict__ Q, const float* __restrict__ K,
                 const float* __restrict__ V, const float* __restrict__ pad,
                 float* __restrict__ O)
{
    extern __shared__ float sm[];
    float* Ks = sm;                 // 64*128
    float* Vs = sm + AM * DH_;      // 64*128
    float* Ss = sm + 2 * AM * DH_;  // 64*64
    float* Pm = Ss + AM * AM;       // 64

    const int tid = threadIdx.x;
    const int q   = tid >> 2;       // 0..63
    const int l4  = tid & 3;        // 0..3
    const int ds  = l4 * 32;

    const int bh = blockIdx.y;
    const int b  = bh >> 4;         // / H_
    const int h  = bh & 15;
    const int g  = h >> 2;          // h / (H/G)
    const int qb = blockIdx.x;
    const int qg = qb * AM + q;

    const float scale = 0.08838834764831845f;  // 1/sqrt(128)

    // Q slice into registers
    float qreg[32];
    {
        const float* qp = Q + (size_t)(b * S_ + qg) * D_ + h * DH_ + ds;
#pragma unroll
        for (int i = 0; i < 32; i += 4) {
            float4 t = *(const float4*)(qp + i);
            qreg[i] = t.x; qreg[i + 1] = t.y; qreg[i + 2] = t.z; qreg[i + 3] = t.w;
        }
    }

    float acc[32];
#pragma unroll
    for (int i = 0; i < 32; i++) acc[i] = 0.0f;
    float m = -1e30f, l = 0.0f;

    const int ntiles = qb + 1;  // causal: only tiles with keys <= last query
    for (int kt = 0; kt < ntiles; kt++) {
        const int krow0 = kt * AM;

        // ---- load K tile (64 x 128) ----
#pragma unroll
        for (int it = 0; it < 8; it++) {
            int f = it * 256 + tid;           // 2048 float4s
            int row = f >> 5;
            int d4 = (f & 31) * 4;
            *(float4*)&Ks[row * DH_ + d4] =
                *(const float4*)(K + (size_t)(b * S_ + krow0 + row) * KV_ + g * DH_ + d4);
        }
        if (tid < AM) Pm[tid] = pad[b * S_ + krow0 + tid];
        __syncthreads();

        // ---- scores: S = Q K^T * scale, causal + padding mask ----
        for (int kk = 0; kk < AM; kk++) {
            const float* kp = &Ks[kk * DH_ + ds];
            float s = 0.0f;
#pragma unroll
            for (int i = 0; i < 32; i++) s += qreg[i] * kp[i];
            s += __shfl_xor_sync(0xffffffffu, s, 1);
            s += __shfl_xor_sync(0xffffffffu, s, 2);
            int kg = krow0 + kk;
            s = s * scale + Pm[kk] * (-1e9f);
            if (kg > qg) s = -1e30f;
            if (l4 == 0) Ss[q * AM + kk] = s;
        }
        __syncthreads();

        // ---- load V tile (reuse pattern) ----
#pragma unroll
        for (int it = 0; it < 8; it++) {
            int f = it * 256 + tid;
            int row = f >> 5;
            int d4 = (f & 31) * 4;
            *(float4*)&Vs[row * DH_ + d4] =
                *(const float4*)(V + (size_t)(b * S_ + krow0 + row) * KV_ + g * DH_ + d4);
        }
        __syncthreads();

        // ---- online softmax + P @ V ----
        float tm = m;
        for (int kk = 0; kk < AM; kk++) tm = fmaxf(tm, Ss[q * AM + kk]);
        float fs = __expf(m - tm);
        m = tm;
        l *= fs;
#pragma unroll
        for (int i = 0; i < 32; i++) acc[i] *= fs;

        for (int kk = 0; kk < AM; kk++) {
            float p = __expf(Ss[q * AM + kk] - m);
            l += p;
            const float* vp = &Vs[kk * DH_ + ds];
#pragma unroll
            for (int i = 0; i < 32; i++) acc[i] += p * vp[i];
        }
        __syncthreads();
    }

    const float inv = 1.0f / l;
    float* op = O + (size_t)(b * S_ + qg) * D_ + h * DH_ + ds;
#pragma unroll
    for (int i = 0; i < 32; i++) op[i] = acc[i] * inv;
}

// ============================== launch =====================================
extern "C" void kernel_launch(void* const* d_in, const int* in_sizes, int n_in,
                              void* d_out, int out_size)
{
    const float* X   = (const float*)d_in[0];
    // d_in[1] = casual_mask (applied analytically)
    const float* pad = (const float*)d_in[2];
    const float* Wq  = (const float*)d_in[3];
    const float* bq  = (const float*)d_in[4];
    const float* Wk  = (const float*)d_in[5];
    const float* bk  = (const float*)d_in[6];
    const float* Wv  = (const float*)d_in[7];
    const float* bv  = (const float*)d_in[8];
    const float* Wo  = (const float*)d_in[9];
    const float* bo  = (const float*)d_in[10];
    float* out = (float*)d_out;

    float *Qb, *Kb, *Vb, *Ob;
    cudaGetSymbolAddress((void**)&Qb, g_Q);
    cudaGetSymbolAddress((void**)&Kb, g_K);
    cudaGetSymbolAddress((void**)&Vb, g_V);
    cudaGetSymbolAddress((void**)&Ob, g_O);

    dim3 tb(256);

    // QKV projections
    gemm_bias_kernel<<<dim3(D_ / BN, MS_ / BM), tb>>>(X, Wq, bq, Qb, MS_, D_, D_);
    gemm_bias_kernel<<<dim3(KV_ / BN, MS_ / BM), tb>>>(X, Wk, bk, Kb, MS_, KV_, D_);
    gemm_bias_kernel<<<dim3(KV_ / BN, MS_ / BM), tb>>>(X, Wv, bv, Vb, MS_, KV_, D_);

    // attention
    size_t smem = (size_t)(2 * AM * DH_ + AM * AM + AM) * sizeof(float); // ~82KB
    cudaFuncSetAttribute(attn_kernel, cudaFuncAttributeMaxDynamicSharedMemorySize, (int)smem);
    attn_kernel<<<dim3(S_ / AM, B_ * H_), tb, smem>>>(Qb, Kb, Vb, pad, Ob);

    // output projection
    gemm_bias_kernel<<<dim3(D_ / BN, MS_ / BM), tb>>>(Ob, Wo, bo, out, MS_, D_, D_);
}

// round 6
// speedup vs baseline: 8.6013x; 8.6013x over previous
#include <cuda_runtime.h>
#include <cuda_bf16.h>
#include <math.h>

// Problem constants
#define B_  2
#define S_  2048
#define D_  2048
#define H_  16
#define G_  4
#define DH_ 128
#define KV_ 512
#define MS_ (B_ * S_)

// -------------------- scratch (device globals; no allocs allowed) ----------
__device__ float g_Q[MS_ * D_];
__device__ float g_K[MS_ * KV_];
__device__ float g_V[MS_ * KV_];
__device__ float g_O[MS_ * D_];

// -------------------- tf32 helpers ----------------------------------------
__device__ __forceinline__ unsigned f2tf(float x) {
    unsigned u;
    asm("cvt.rna.tf32.f32 %0, %1;" : "=r"(u) : "f"(x));
    return u;
}

__device__ __forceinline__ void mma_tf32(float c[4], const unsigned a[4],
                                         unsigned b0, unsigned b1) {
    asm volatile(
        "mma.sync.aligned.m16n8k8.row.col.f32.tf32.tf32.f32 "
        "{%0,%1,%2,%3},{%4,%5,%6,%7},{%8,%9},{%0,%1,%2,%3};"
        : "+f"(c[0]), "+f"(c[1]), "+f"(c[2]), "+f"(c[3])
        : "r"(a[0]), "r"(a[1]), "r"(a[2]), "r"(a[3]), "r"(b0), "r"(b1));
}

// ======================= TF32 GEMM: C = A[M,K] @ W[K,N] + bias =============
// 128x128 tile, BK=16, 256 threads (8 warps as 4x2), warp tile 32x64.
#define GBM 128
#define GBN 128
#define GBK 16

__global__ __launch_bounds__(256)
void gemm_tf32_kernel(const float* __restrict__ A, const float* __restrict__ W,
                      const float* __restrict__ bias, float* __restrict__ C,
                      int M, int N, int K)
{
    __shared__ unsigned As[GBK][GBM + 4];   // As[k][m] (transposed)
    __shared__ unsigned Bs[GBK][GBN + 4];   // Bs[k][n]

    const int tid = threadIdx.x;
    const int w   = tid >> 5;
    const int lane = tid & 31;
    const int r  = lane >> 2;     // 0..7
    const int tg = lane & 3;      // 0..3
    const int wm = (w >> 1) * 32; // warp M origin (4 warps)
    const int wn = (w & 1) * 64;  // warp N origin (2 warps)

    const int bm = blockIdx.y * GBM;
    const int bn = blockIdx.x * GBN;

    // A loader: 128x16 tile = 512 float4, 2 per thread
    const int aRow = tid >> 2;          // 0..63  (second: +64)
    const int aC4  = (tid & 3) * 4;     // 0,4,8,12
    // B loader: 16x128 tile = 512 float4, 2 per thread
    const int bRow = tid >> 5;          // 0..7   (second: +8)
    const int bC4  = (tid & 31) * 4;    // 0..124

    const float* Ap0 = A + (size_t)(bm + aRow) * K + aC4;
    const float* Ap1 = A + (size_t)(bm + aRow + 64) * K + aC4;
    const float* Bp0 = W + (size_t)bRow * N + bn + bC4;
    const float* Bp1 = W + (size_t)(bRow + 8) * N + bn + bC4;

    float acc[2][8][4];
#pragma unroll
    for (int mt = 0; mt < 2; mt++)
#pragma unroll
        for (int nt = 0; nt < 8; nt++)
#pragma unroll
            for (int j = 0; j < 4; j++) acc[mt][nt][j] = 0.0f;

    // prologue: load tile 0, stage to smem
    float4 ra0 = *(const float4*)Ap0;
    float4 ra1 = *(const float4*)Ap1;
    float4 rb0 = *(const float4*)Bp0;
    float4 rb1 = *(const float4*)Bp1;
    {
        As[aC4 + 0][aRow] = f2tf(ra0.x); As[aC4 + 1][aRow] = f2tf(ra0.y);
        As[aC4 + 2][aRow] = f2tf(ra0.z); As[aC4 + 3][aRow] = f2tf(ra0.w);
        As[aC4 + 0][aRow + 64] = f2tf(ra1.x); As[aC4 + 1][aRow + 64] = f2tf(ra1.y);
        As[aC4 + 2][aRow + 64] = f2tf(ra1.z); As[aC4 + 3][aRow + 64] = f2tf(ra1.w);
        uint4 u0 = {f2tf(rb0.x), f2tf(rb0.y), f2tf(rb0.z), f2tf(rb0.w)};
        uint4 u1 = {f2tf(rb1.x), f2tf(rb1.y), f2tf(rb1.z), f2tf(rb1.w)};
        *(uint4*)&Bs[bRow][bC4] = u0;
        *(uint4*)&Bs[bRow + 8][bC4] = u1;
    }
    __syncthreads();

    for (int k0 = 0; k0 < K; k0 += GBK) {
        const bool has_next = (k0 + GBK) < K;
        if (has_next) {
            ra0 = *(const float4*)(Ap0 + k0 + GBK);
            ra1 = *(const float4*)(Ap1 + k0 + GBK);
            rb0 = *(const float4*)(Bp0 + (size_t)(k0 + GBK) * N);
            rb1 = *(const float4*)(Bp1 + (size_t)(k0 + GBK) * N);
        }

        // compute from smem: 2 k-steps of 8
#pragma unroll
        for (int ks = 0; ks < 2; ks++) {
            const int k = ks * 8;
            unsigned afr[2][4];
#pragma unroll
            for (int mt = 0; mt < 2; mt++) {
                const int m0 = wm + mt * 16;
                afr[mt][0] = As[k + tg][m0 + r];
                afr[mt][1] = As[k + tg][m0 + r + 8];
                afr[mt][2] = As[k + tg + 4][m0 + r];
                afr[mt][3] = As[k + tg + 4][m0 + r + 8];
            }
#pragma unroll
            for (int nt = 0; nt < 8; nt++) {
                const int n0 = wn + nt * 8;
                unsigned b0 = Bs[k + tg][n0 + r];
                unsigned b1 = Bs[k + tg + 4][n0 + r];
                mma_tf32(acc[0][nt], afr[0], b0, b1);
                mma_tf32(acc[1][nt], afr[1], b0, b1);
            }
        }

        if (has_next) {
            __syncthreads();
            As[aC4 + 0][aRow] = f2tf(ra0.x); As[aC4 + 1][aRow] = f2tf(ra0.y);
            As[aC4 + 2][aRow] = f2tf(ra0.z); As[aC4 + 3][aRow] = f2tf(ra0.w);
            As[aC4 + 0][aRow + 64] = f2tf(ra1.x); As[aC4 + 1][aRow + 64] = f2tf(ra1.y);
            As[aC4 + 2][aRow + 64] = f2tf(ra1.z); As[aC4 + 3][aRow + 64] = f2tf(ra1.w);
            uint4 u0 = {f2tf(rb0.x), f2tf(rb0.y), f2tf(rb0.z), f2tf(rb0.w)};
            uint4 u1 = {f2tf(rb1.x), f2tf(rb1.y), f2tf(rb1.z), f2tf(rb1.w)};
            *(uint4*)&Bs[bRow][bC4] = u0;
            *(uint4*)&Bs[bRow + 8][bC4] = u1;
            __syncthreads();
        }
    }

    // epilogue
#pragma unroll
    for (int mt = 0; mt < 2; mt++) {
        const int row0 = bm + wm + mt * 16 + r;
#pragma unroll
        for (int nt = 0; nt < 8; nt++) {
            const int col = bn + wn + nt * 8 + 2 * tg;
            float2 v0 = {acc[mt][nt][0] + bias[col], acc[mt][nt][1] + bias[col + 1]};
            float2 v1 = {acc[mt][nt][2] + bias[col], acc[mt][nt][3] + bias[col + 1]};
            *(float2*)&C[(size_t)row0 * N + col] = v0;
            *(float2*)&C[(size_t)(row0 + 8) * N + col] = v1;
        }
    }
}

// ======================= TF32 Flash attention (causal, GQA) ================
// Block: 128 queries x one (b,h). 256 threads = 8 warps; warp owns 16 q-rows.
// Key tiles of 64. Q fragments register-resident (K=128 -> 16 k-steps).
#define QT 128
#define KT 64

// smem partition (in unsigned words):
//   Ks: 64 x 132   (key-major [key][dh], +4 pad)
//   Vs: 64 x 132
//   Ps: 128 x 68   (P tile / Q staging, [row][col], +4 pad)
//   Pm: 64 floats  (padding mask)
#define KS_STRIDE 132
#define PS_STRIDE 68
#define SM_KS 0
#define SM_VS (SM_KS + 64 * KS_STRIDE)
#define SM_PS (SM_VS + 64 * KS_STRIDE)
#define SM_PM (SM_PS + 128 * PS_STRIDE)
#define SM_TOTAL (SM_PM + 64)

__global__ __launch_bounds__(256)
void attn_tf32_kernel(const float* __restrict__ Q, const float* __restrict__ K,
                      const float* __restrict__ V, const float* __restrict__ pad,
                      float* __restrict__ O)
{
    extern __shared__ unsigned smu[];
    unsigned* Ks = smu + SM_KS;
    unsigned* Vs = smu + SM_VS;
    unsigned* Ps = smu + SM_PS;
    float*    Pm = (float*)(smu + SM_PM);

    const int tid  = threadIdx.x;
    const int w    = tid >> 5;
    const int lane = tid & 31;
    const int r    = lane >> 2;
    const int tg   = lane & 3;
    const int q0   = w * 16;       // warp's query-row base within block

    const int bh = blockIdx.y;
    const int b  = bh >> 4;
    const int h  = bh & 15;
    const int g  = h >> 2;
    const int qb = blockIdx.x;

    const int qg0 = qb * QT + q0 + r;     // global query rows handled by thread
    const int qg1 = qg0 + 8;

    const float scale = 0.08838834764831845f;  // 1/sqrt(128)

    // ---- stage Q through smem (Ps buffer), pull fragments into registers ----
    unsigned qf[16][4];
#pragma unroll
    for (int half = 0; half < 2; half++) {
#pragma unroll
        for (int it = 0; it < 8; it++) {
            int f = it * 256 + tid;
            int row = f >> 4;
            int c4 = (f & 15) * 4;
            float4 v = *(const float4*)(Q + (size_t)(b * S_ + qb * QT + row) * D_
                                          + h * DH_ + half * 64 + c4);
            uint4 u = {f2tf(v.x), f2tf(v.y), f2tf(v.z), f2tf(v.w)};
            *(uint4*)&Ps[row * PS_STRIDE + c4] = u;
        }
        __syncthreads();
#pragma unroll
        for (int ks = 0; ks < 8; ks++) {
            int kk = half * 8 + ks;
            qf[kk][0] = Ps[(q0 + r) * PS_STRIDE + ks * 8 + tg];
            qf[kk][1] = Ps[(q0 + r + 8) * PS_STRIDE + ks * 8 + tg];
            qf[kk][2] = Ps[(q0 + r) * PS_STRIDE + ks * 8 + tg + 4];
            qf[kk][3] = Ps[(q0 + r + 8) * PS_STRIDE + ks * 8 + tg + 4];
        }
        __syncthreads();
    }

    float oacc[16][4];
#pragma unroll
    for (int nt = 0; nt < 16; nt++)
#pragma unroll
        for (int j = 0; j < 4; j++) oacc[nt][j] = 0.0f;
    float m0 = -1e30f, m1 = -1e30f, l0 = 0.0f, l1 = 0.0f;

    const int ntiles = 2 * qb + 2;  // causal
    for (int kt = 0; kt < ntiles; kt++) {
        const int krow0 = kt * KT;

        // ---- load K & V tiles (64 x 128), tf32-converted, natural layout ----
#pragma unroll
        for (int it = 0; it < 8; it++) {
            int f = it * 256 + tid;
            int row = f >> 5;
            int d4 = (f & 31) * 4;
            float4 kv = *(const float4*)(K + (size_t)(b * S_ + krow0 + row) * KV_
                                           + g * DH_ + d4);
            float4 vv = *(const float4*)(V + (size_t)(b * S_ + krow0 + row) * KV_
                                           + g * DH_ + d4);
            uint4 ku = {f2tf(kv.x), f2tf(kv.y), f2tf(kv.z), f2tf(kv.w)};
            uint4 vu = {f2tf(vv.x), f2tf(vv.y), f2tf(vv.z), f2tf(vv.w)};
            *(uint4*)&Ks[row * KS_STRIDE + d4] = ku;
            *(uint4*)&Vs[row * KS_STRIDE + d4] = vu;
        }
        if (tid < 64) Pm[tid] = pad[b * S_ + krow0 + tid];
        __syncthreads();

        // ---- S = Q K^T  (A = Q frags, B = Ks[key][dh] as col-major k=dh,n=key)
        float sacc[8][4];
#pragma unroll
        for (int nt = 0; nt < 8; nt++)
#pragma unroll
            for (int j = 0; j < 4; j++) sacc[nt][j] = 0.0f;

#pragma unroll
        for (int ks = 0; ks < 16; ks++) {
#pragma unroll
            for (int nt = 0; nt < 8; nt++) {
                unsigned b0 = Ks[(nt * 8 + r) * KS_STRIDE + ks * 8 + tg];
                unsigned b1 = Ks[(nt * 8 + r) * KS_STRIDE + ks * 8 + tg + 4];
                mma_tf32(sacc[nt], qf[ks], b0, b1);
            }
        }

        // ---- mask + scale ----
#pragma unroll
        for (int nt = 0; nt < 8; nt++) {
#pragma unroll
            for (int j = 0; j < 4; j++) {
                int col = nt * 8 + 2 * tg + (j & 1);
                int rowg = (j < 2) ? qg0 : qg1;
                int kg = krow0 + col;
                float s = sacc[nt][j] * scale + Pm[col] * (-1e9f);
                if (kg > rowg) s = -1e30f;
                sacc[nt][j] = s;
            }
        }

        // ---- online softmax (rows r, r+8; stats replicated in lane quad) ----
        float tm0 = -1e30f, tm1 = -1e30f;
#pragma unroll
        for (int nt = 0; nt < 8; nt++) {
            tm0 = fmaxf(tm0, fmaxf(sacc[nt][0], sacc[nt][1]));
            tm1 = fmaxf(tm1, fmaxf(sacc[nt][2], sacc[nt][3]));
        }
        tm0 = fmaxf(tm0, __shfl_xor_sync(0xffffffffu, tm0, 1));
        tm0 = fmaxf(tm0, __shfl_xor_sync(0xffffffffu, tm0, 2));
        tm1 = fmaxf(tm1, __shfl_xor_sync(0xffffffffu, tm1, 1));
        tm1 = fmaxf(tm1, __shfl_xor_sync(0xffffffffu, tm1, 2));

        float mn0 = fmaxf(m0, tm0), mn1 = fmaxf(m1, tm1);
        float f0 = __expf(m0 - mn0), f1 = __expf(m1 - mn1);
        m0 = mn0; m1 = mn1;
        l0 *= f0; l1 *= f1;
#pragma unroll
        for (int nt = 0; nt < 16; nt++) {
            oacc[nt][0] *= f0; oacc[nt][1] *= f0;
            oacc[nt][2] *= f1; oacc[nt][3] *= f1;
        }

        float ps0 = 0.0f, ps1 = 0.0f;
#pragma unroll
        for (int nt = 0; nt < 8; nt++) {
            int col = nt * 8 + 2 * tg;
            float p0 = __expf(sacc[nt][0] - m0);
            float p1 = __expf(sacc[nt][1] - m0);
            float p2 = __expf(sacc[nt][2] - m1);
            float p3 = __expf(sacc[nt][3] - m1);
            ps0 += p0 + p1; ps1 += p2 + p3;
            Ps[(q0 + r) * PS_STRIDE + col]     = f2tf(p0);
            Ps[(q0 + r) * PS_STRIDE + col + 1] = f2tf(p1);
            Ps[(q0 + r + 8) * PS_STRIDE + col]     = f2tf(p2);
            Ps[(q0 + r + 8) * PS_STRIDE + col + 1] = f2tf(p3);
        }
        ps0 += __shfl_xor_sync(0xffffffffu, ps0, 1);
        ps0 += __shfl_xor_sync(0xffffffffu, ps0, 2);
        ps1 += __shfl_xor_sync(0xffffffffu, ps1, 1);
        ps1 += __shfl_xor_sync(0xffffffffu, ps1, 2);
        l0 += ps0; l1 += ps1;
        __syncwarp();   // P rows are warp-private: warp fence is enough

        // ---- O += P V  (A = Ps frags, B = Vs[key][dh] as k=key, n=dh) ----
#pragma unroll
        for (int ks = 0; ks < 8; ks++) {
            unsigned a[4];
            a[0] = Ps[(q0 + r) * PS_STRIDE + ks * 8 + tg];
            a[1] = Ps[(q0 + r + 8) * PS_STRIDE + ks * 8 + tg];
            a[2] = Ps[(q0 + r) * PS_STRIDE + ks * 8 + tg + 4];
            a[3] = Ps[(q0 + r + 8) * PS_STRIDE + ks * 8 + tg + 4];
#pragma unroll
            for (int nt = 0; nt < 16; nt++) {
                unsigned b0 = Vs[(ks * 8 + tg) * KS_STRIDE + nt * 8 + r];
                unsigned b1 = Vs[(ks * 8 + tg + 4) * KS_STRIDE + nt * 8 + r];
                mma_tf32(oacc[nt], a, b0, b1);
            }
        }
        __syncthreads();   // before next tile overwrites Ks/Vs
    }

    // ---- epilogue: O / l ----
    const float inv0 = 1.0f / l0, inv1 = 1.0f / l1;
    float* op0 = O + (size_t)(b * S_ + qg0) * D_ + h * DH_;
    float* op1 = O + (size_t)(b * S_ + qg1) * D_ + h * DH_;
#pragma unroll
    for (int nt = 0; nt < 16; nt++) {
        int col = nt * 8 + 2 * tg;
        float2 v0 = {oacc[nt][0] * inv0, oacc[nt][1] * inv0};
        float2 v1 = {oacc[nt][2] * inv1, oacc[nt][3] * inv1};
        *(float2*)(op0 + col) = v0;
        *(float2*)(op1 + col) = v1;
    }
}

// ============================== launch =====================================
extern "C" void kernel_launch(void* const* d_in, const int* in_sizes, int n_in,
                              void* d_out, int out_size)
{
    const float* X   = (const float*)d_in[0];
    // d_in[1] = causal mask (applied analytically)
    const float* pad = (const float*)d_in[2];
    const float* Wq  = (const float*)d_in[3];
    const float* bq  = (const float*)d_in[4];
    const float* Wk  = (const float*)d_in[5];
    const float* bk  = (const float*)d_in[6];
    const float* Wv  = (const float*)d_in[7];
    const float* bv  = (const float*)d_in[8];
    const float* Wo  = (const float*)d_in[9];
    const float* bo  = (const float*)d_in[10];
    float* out = (float*)d_out;

    float *Qb, *Kb, *Vb, *Ob;
    cudaGetSymbolAddress((void**)&Qb, g_Q);
    cudaGetSymbolAddress((void**)&Kb, g_K);
    cudaGetSymbolAddress((void**)&Vb, g_V);
    cudaGetSymbolAddress((void**)&Ob, g_O);

    dim3 tb(256);

    // QKV projections (tf32 tensor cores)
    gemm_tf32_kernel<<<dim3(D_ / GBN, MS_ / GBM), tb>>>(X, Wq, bq, Qb, MS_, D_, D_);
    gemm_tf32_kernel<<<dim3(KV_ / GBN, MS_ / GBM), tb>>>(X, Wk, bk, Kb, MS_, KV_, D_);
    gemm_tf32_kernel<<<dim3(KV_ / GBN, MS_ / GBM), tb>>>(X, Wv, bv, Vb, MS_, KV_, D_);

    // attention
    size_t smem = (size_t)SM_TOTAL * sizeof(unsigned);  // ~100 KB
    cudaFuncSetAttribute(attn_tf32_kernel,
                         cudaFuncAttributeMaxDynamicSharedMemorySize, (int)smem);
    attn_tf32_kernel<<<dim3(S_ / QT, B_ * H_), tb, smem>>>(Qb, Kb, Vb, pad, Ob);

    // output projection
    gemm_tf32_kernel<<<dim3(D_ / GBN, MS_ / GBM), tb>>>(Ob, Wo, bo, out, MS_, D_, D_);
}

// round 7
// speedup vs baseline: 9.3013x; 1.0814x over previous
#include <cuda_runtime.h>
#include <cuda_bf16.h>
#include <math.h>

// Problem constants
#define B_  2
#define S_  2048
#define D_  2048
#define H_  16
#define G_  4
#define DH_ 128
#define KV_ 512
#define MS_ (B_ * S_)

// -------------------- scratch (device globals; no allocs allowed) ----------
__device__ float g_Q[MS_ * D_];
__device__ float g_K[MS_ * KV_];
__device__ float g_V[MS_ * KV_];
__device__ float g_O[MS_ * D_];

// -------------------- helpers ----------------------------------------------
__device__ __forceinline__ unsigned f2tf(float x) {
    unsigned u;
    asm("cvt.rna.tf32.f32 %0, %1;" : "=r"(u) : "f"(x));
    return u;
}

__device__ __forceinline__ void mma_tf32(float c[4], const unsigned a[4],
                                         unsigned b0, unsigned b1) {
    asm volatile(
        "mma.sync.aligned.m16n8k8.row.col.f32.tf32.tf32.f32 "
        "{%0,%1,%2,%3},{%4,%5,%6,%7},{%8,%9},{%0,%1,%2,%3};"
        : "+f"(c[0]), "+f"(c[1]), "+f"(c[2]), "+f"(c[3])
        : "r"(a[0]), "r"(a[1]), "r"(a[2]), "r"(a[3]), "r"(b0), "r"(b1));
}

__device__ __forceinline__ void cp16(void* sdst, const void* gsrc) {
    unsigned sa = (unsigned)__cvta_generic_to_shared(sdst);
    asm volatile("cp.async.cg.shared.global [%0], [%1], 16;" :: "r"(sa), "l"(gsrc));
}
#define CP_COMMIT() asm volatile("cp.async.commit_group;")
template<int N> __device__ __forceinline__ void cp_wait() {
    asm volatile("cp.async.wait_group %0;" :: "n"(N));
}

// ======================= TF32 GEMM: C = A[M,K] @ W[K,N] + bias =============
// 128x128 tile, BK=16, 256 threads (8 warps as 4x2), warp tile 32x64.
// 3-stage cp.async pipeline; raw fp32 in smem, tf32 cvt at fragment load.
#define GBM 128
#define GBN 128
#define GBK 16
#define GA_STRIDE 20     // 16 + 4 pad  (A stored [m][k])
#define GB_STRIDE 136    // 128 + 8 pad (B stored [k][n])
#define G_STAGE (GBM * GA_STRIDE + GBK * GB_STRIDE)   // 2560 + 2176 = 4736 words
#define G_NSTAGE 3

__global__ __launch_bounds__(256)
void gemm_tf32_kernel(const float* __restrict__ A, const float* __restrict__ W,
                      const float* __restrict__ bias, float* __restrict__ C,
                      int M, int N, int K)
{
    extern __shared__ float gsm[];

    const int tid  = threadIdx.x;
    const int w    = tid >> 5;
    const int lane = tid & 31;
    const int r    = lane >> 2;
    const int tg   = lane & 3;
    const int wm   = (w >> 1) * 32;
    const int wn   = (w & 1) * 64;

    const int bm = blockIdx.y * GBM;
    const int bn = blockIdx.x * GBN;

    // A loader: row = tid>>1 (0..127), two 16B chunks at cols (tid&1)*8 {+0,+4}
    const int aRow = tid >> 1;
    const int aCol = (tid & 1) * 8;
    // B loader: row = tid>>4 (0..15), two 16B chunks at cols (tid&15)*8 {+0,+4}
    const int bRow = tid >> 4;
    const int bCol = (tid & 15) * 8;

    const float* Ap = A + (size_t)(bm + aRow) * K + aCol;
    const float* Bp = W + (size_t)bRow * N + bn + bCol;

    float acc[2][8][4];
#pragma unroll
    for (int mt = 0; mt < 2; mt++)
#pragma unroll
        for (int nt = 0; nt < 8; nt++)
#pragma unroll
            for (int j = 0; j < 4; j++) acc[mt][nt][j] = 0.0f;

    // issue one stage's loads
    auto issue = [&](int stage, int k0) {
        float* As = gsm + stage * G_STAGE;
        float* Bs = As + GBM * GA_STRIDE;
        cp16(&As[aRow * GA_STRIDE + aCol],     Ap + k0);
        cp16(&As[aRow * GA_STRIDE + aCol + 4], Ap + k0 + 4);
        cp16(&Bs[bRow * GB_STRIDE + bCol],     Bp + (size_t)k0 * N);
        cp16(&Bs[bRow * GB_STRIDE + bCol + 4], Bp + (size_t)k0 * N + 4);
    };

    // prologue: 2 stages in flight
    issue(0, 0);       CP_COMMIT();
    issue(1, GBK);     CP_COMMIT();

    int stage = 0;
    for (int k0 = 0; k0 < K; k0 += GBK) {
        cp_wait<1>();          // current stage has landed
        __syncthreads();       // visible to all; prev compute finished everywhere

        int knext = k0 + 2 * GBK;
        if (knext < K) {
            int ws = stage + 2; if (ws >= G_NSTAGE) ws -= G_NSTAGE;
            issue(ws, knext);
        }
        CP_COMMIT();           // always commit (possibly empty) to keep counts aligned

        const float* As = gsm + stage * G_STAGE;
        const float* Bs = As + GBM * GA_STRIDE;
#pragma unroll
        for (int ks = 0; ks < 2; ks++) {
            const int k = ks * 8;
            unsigned afr[2][4];
#pragma unroll
            for (int mt = 0; mt < 2; mt++) {
                const int m0 = wm + mt * 16;
                afr[mt][0] = f2tf(As[(m0 + r) * GA_STRIDE + k + tg]);
                afr[mt][1] = f2tf(As[(m0 + r + 8) * GA_STRIDE + k + tg]);
                afr[mt][2] = f2tf(As[(m0 + r) * GA_STRIDE + k + tg + 4]);
                afr[mt][3] = f2tf(As[(m0 + r + 8) * GA_STRIDE + k + tg + 4]);
            }
#pragma unroll
            for (int nt = 0; nt < 8; nt++) {
                const int n0 = wn + nt * 8;
                unsigned b0 = f2tf(Bs[(k + tg) * GB_STRIDE + n0 + r]);
                unsigned b1 = f2tf(Bs[(k + tg + 4) * GB_STRIDE + n0 + r]);
                mma_tf32(acc[0][nt], afr[0], b0, b1);
                mma_tf32(acc[1][nt], afr[1], b0, b1);
            }
        }
        stage++; if (stage >= G_NSTAGE) stage = 0;
    }

    // epilogue
#pragma unroll
    for (int mt = 0; mt < 2; mt++) {
        const int row0 = bm + wm + mt * 16 + r;
#pragma unroll
        for (int nt = 0; nt < 8; nt++) {
            const int col = bn + wn + nt * 8 + 2 * tg;
            float2 v0 = {acc[mt][nt][0] + bias[col], acc[mt][nt][1] + bias[col + 1]};
            float2 v1 = {acc[mt][nt][2] + bias[col], acc[mt][nt][3] + bias[col + 1]};
            *(float2*)&C[(size_t)row0 * N + col] = v0;
            *(float2*)&C[(size_t)(row0 + 8) * N + col] = v1;
        }
    }
}

// ======================= TF32 Flash attention (causal, GQA) ================
// Block: 128 queries x one (b,h). 256 threads = 8 warps; warp owns 16 q-rows.
// cp.async double-buffered K/V tiles (raw fp32), tf32 cvt at fragment load.
#define QT 128
#define KT 64
#define AKS 136      // K/V smem row stride (128 + 8 pad -> conflict-free frags)
#define PS_STRIDE 68

// word offsets within dynamic smem
#define SMA_K 0
#define SMA_V (SMA_K + 2 * KT * AKS)            // 17408
#define SMA_P (SMA_V + 2 * KT * AKS)            // 34816
#define SMA_M (SMA_P + QT * PS_STRIDE)          // 43520
#define SMA_TOT (SMA_M + 2 * KT)                // 43648 words = 174.6 KB

__global__ __launch_bounds__(256)
void attn_tf32_kernel(const float* __restrict__ Q, const float* __restrict__ K,
                      const float* __restrict__ V, const float* __restrict__ pad,
                      float* __restrict__ O)
{
    extern __shared__ float asm_f[];
    float*    Ksf = asm_f + SMA_K;
    float*    Vsf = asm_f + SMA_V;
    unsigned* Ps  = (unsigned*)(asm_f + SMA_P);
    float*    Pmf = asm_f + SMA_M;

    const int tid  = threadIdx.x;
    const int w    = tid >> 5;
    const int lane = tid & 31;
    const int r    = lane >> 2;
    const int tg   = lane & 3;
    const int q0   = w * 16;

    const int bh = blockIdx.y;
    const int b  = bh >> 4;
    const int h  = bh & 15;
    const int g  = h >> 2;
    // reverse mapping: longest (most tiles) blocks scheduled in wave 1
    const int qb = gridDim.x - 1 - blockIdx.x;

    const int qg0 = qb * QT + q0 + r;
    const int qg1 = qg0 + 8;

    const float scale = 0.08838834764831845f;  // 1/sqrt(128)

    const float* Kbase = K + (size_t)b * S_ * KV_ + g * DH_;
    const float* Vbase = V + (size_t)b * S_ * KV_ + g * DH_;

    // issue K/V (+mask) tile loads into buffer `buf`
    auto issue_kv = [&](int buf, int krow0) {
        float* Kd = Ksf + buf * KT * AKS;
        float* Vd = Vsf + buf * KT * AKS;
#pragma unroll
        for (int it = 0; it < 8; it++) {
            int f = it * 256 + tid;
            int row = f >> 5;
            int c4 = (f & 31) * 4;
            cp16(&Kd[row * AKS + c4], Kbase + (size_t)(krow0 + row) * KV_ + c4);
            cp16(&Vd[row * AKS + c4], Vbase + (size_t)(krow0 + row) * KV_ + c4);
        }
        if (tid < 16)
            cp16(&Pmf[buf * KT + tid * 4], pad + b * S_ + krow0 + tid * 4);
    };

    const int ntiles = 2 * qb + 2;  // causal

    // prologue: tile 0 in flight while we stage Q
    issue_kv(0, 0);
    CP_COMMIT();

    // ---- stage Q through smem (Ps buffer), pull tf32 fragments to regs ----
    unsigned qf[16][4];
#pragma unroll
    for (int half = 0; half < 2; half++) {
#pragma unroll
        for (int it = 0; it < 8; it++) {
            int f = it * 256 + tid;
            int row = f >> 4;
            int c4 = (f & 15) * 4;
            float4 v = *(const float4*)(Q + (size_t)(b * S_ + qb * QT + row) * D_
                                          + h * DH_ + half * 64 + c4);
            uint4 u = {f2tf(v.x), f2tf(v.y), f2tf(v.z), f2tf(v.w)};
            *(uint4*)&Ps[row * PS_STRIDE + c4] = u;
        }
        __syncthreads();
#pragma unroll
        for (int ks = 0; ks < 8; ks++) {
            int kk = half * 8 + ks;
            qf[kk][0] = Ps[(q0 + r) * PS_STRIDE + ks * 8 + tg];
            qf[kk][1] = Ps[(q0 + r + 8) * PS_STRIDE + ks * 8 + tg];
            qf[kk][2] = Ps[(q0 + r) * PS_STRIDE + ks * 8 + tg + 4];
            qf[kk][3] = Ps[(q0 + r + 8) * PS_STRIDE + ks * 8 + tg + 4];
        }
        __syncthreads();
    }

    float oacc[16][4];
#pragma unroll
    for (int nt = 0; nt < 16; nt++)
#pragma unroll
        for (int j = 0; j < 4; j++) oacc[nt][j] = 0.0f;
    float m0 = -1e30f, m1 = -1e30f, l0 = 0.0f, l1 = 0.0f;

    for (int kt = 0; kt < ntiles; kt++) {
        const int buf   = kt & 1;
        const int krow0 = kt * KT;

        cp_wait<0>();          // tile kt landed
        __syncthreads();       // visible everywhere; prev compute done everywhere

        if (kt + 1 < ntiles) issue_kv(buf ^ 1, krow0 + KT);
        CP_COMMIT();

        const float* Kt = Ksf + buf * KT * AKS;
        const float* Vt = Vsf + buf * KT * AKS;
        const float* Pm = Pmf + buf * KT;

        // ---- S = Q K^T ----
        float sacc[8][4];
#pragma unroll
        for (int nt = 0; nt < 8; nt++)
#pragma unroll
            for (int j = 0; j < 4; j++) sacc[nt][j] = 0.0f;

#pragma unroll
        for (int ks = 0; ks < 16; ks++) {
#pragma unroll
            for (int nt = 0; nt < 8; nt++) {
                unsigned b0 = f2tf(Kt[(nt * 8 + r) * AKS + ks * 8 + tg]);
                unsigned b1 = f2tf(Kt[(nt * 8 + r) * AKS + ks * 8 + tg + 4]);
                mma_tf32(sacc[nt], qf[ks], b0, b1);
            }
        }

        // ---- mask + scale ----
#pragma unroll
        for (int nt = 0; nt < 8; nt++) {
#pragma unroll
            for (int j = 0; j < 4; j++) {
                int col = nt * 8 + 2 * tg + (j & 1);
                int rowg = (j < 2) ? qg0 : qg1;
                int kg = krow0 + col;
                float s = sacc[nt][j] * scale + Pm[col] * (-1e9f);
                if (kg > rowg) s = -1e30f;
                sacc[nt][j] = s;
            }
        }

        // ---- online softmax ----
        float tm0 = -1e30f, tm1 = -1e30f;
#pragma unroll
        for (int nt = 0; nt < 8; nt++) {
            tm0 = fmaxf(tm0, fmaxf(sacc[nt][0], sacc[nt][1]));
            tm1 = fmaxf(tm1, fmaxf(sacc[nt][2], sacc[nt][3]));
        }
        tm0 = fmaxf(tm0, __shfl_xor_sync(0xffffffffu, tm0, 1));
        tm0 = fmaxf(tm0, __shfl_xor_sync(0xffffffffu, tm0, 2));
        tm1 = fmaxf(tm1, __shfl_xor_sync(0xffffffffu, tm1, 1));
        tm1 = fmaxf(tm1, __shfl_xor_sync(0xffffffffu, tm1, 2));

        float mn0 = fmaxf(m0, tm0), mn1 = fmaxf(m1, tm1);
        float f0 = __expf(m0 - mn0), f1 = __expf(m1 - mn1);
        m0 = mn0; m1 = mn1;
        l0 *= f0; l1 *= f1;
#pragma unroll
        for (int nt = 0; nt < 16; nt++) {
            oacc[nt][0] *= f0; oacc[nt][1] *= f0;
            oacc[nt][2] *= f1; oacc[nt][3] *= f1;
        }

        float ps0 = 0.0f, ps1 = 0.0f;
#pragma unroll
        for (int nt = 0; nt < 8; nt++) {
            int col = nt * 8 + 2 * tg;
            float p0 = __expf(sacc[nt][0] - m0);
            float p1 = __expf(sacc[nt][1] - m0);
            float p2 = __expf(sacc[nt][2] - m1);
            float p3 = __expf(sacc[nt][3] - m1);
            ps0 += p0 + p1; ps1 += p2 + p3;
            Ps[(q0 + r) * PS_STRIDE + col]         = f2tf(p0);
            Ps[(q0 + r) * PS_STRIDE + col + 1]     = f2tf(p1);
            Ps[(q0 + r + 8) * PS_STRIDE + col]     = f2tf(p2);
            Ps[(q0 + r + 8) * PS_STRIDE + col + 1] = f2tf(p3);
        }
        ps0 += __shfl_xor_sync(0xffffffffu, ps0, 1);
        ps0 += __shfl_xor_sync(0xffffffffu, ps0, 2);
        ps1 += __shfl_xor_sync(0xffffffffu, ps1, 1);
        ps1 += __shfl_xor_sync(0xffffffffu, ps1, 2);
        l0 += ps0; l1 += ps1;
        __syncwarp();   // P rows are warp-private

        // ---- O += P V ----
#pragma unroll
        for (int ks = 0; ks < 8; ks++) {
            unsigned a[4];
            a[0] = Ps[(q0 + r) * PS_STRIDE + ks * 8 + tg];
            a[1] = Ps[(q0 + r + 8) * PS_STRIDE + ks * 8 + tg];
            a[2] = Ps[(q0 + r) * PS_STRIDE + ks * 8 + tg + 4];
            a[3] = Ps[(q0 + r + 8) * PS_STRIDE + ks * 8 + tg + 4];
#pragma unroll
            for (int nt = 0; nt < 16; nt++) {
                unsigned b0 = f2tf(Vt[(ks * 8 + tg) * AKS + nt * 8 + r]);
                unsigned b1 = f2tf(Vt[(ks * 8 + tg + 4) * AKS + nt * 8 + r]);
                mma_tf32(oacc[nt], a, b0, b1);
            }
        }
        // no bottom sync: next iteration's top __syncthreads covers buffer reuse
    }

    // ---- epilogue ----
    const float inv0 = 1.0f / l0, inv1 = 1.0f / l1;
    float* op0 = O + (size_t)(b * S_ + qg0) * D_ + h * DH_;
    float* op1 = O + (size_t)(b * S_ + qg1) * D_ + h * DH_;
#pragma unroll
    for (int nt = 0; nt < 16; nt++) {
        int col = nt * 8 + 2 * tg;
        float2 v0 = {oacc[nt][0] * inv0, oacc[nt][1] * inv0};
        float2 v1 = {oacc[nt][2] * inv1, oacc[nt][3] * inv1};
        *(float2*)(op0 + col) = v0;
        *(float2*)(op1 + col) = v1;
    }
}

// ============================== launch =====================================
extern "C" void kernel_launch(void* const* d_in, const int* in_sizes, int n_in,
                              void* d_out, int out_size)
{
    const float* X   = (const float*)d_in[0];
    // d_in[1] = causal mask (applied analytically)
    const float* pad = (const float*)d_in[2];
    const float* Wq  = (const float*)d_in[3];
    const float* bq  = (const float*)d_in[4];
    const float* Wk  = (const float*)d_in[5];
    const float* bk  = (const float*)d_in[6];
    const float* Wv  = (const float*)d_in[7];
    const float* bv  = (const float*)d_in[8];
    const float* Wo  = (const float*)d_in[9];
    const float* bo  = (const float*)d_in[10];
    float* out = (float*)d_out;

    float *Qb, *Kb, *Vb, *Ob;
    cudaGetSymbolAddress((void**)&Qb, g_Q);
    cudaGetSymbolAddress((void**)&Kb, g_K);
    cudaGetSymbolAddress((void**)&Vb, g_V);
    cudaGetSymbolAddress((void**)&Ob, g_O);

    dim3 tb(256);

    size_t gsmem = (size_t)(G_NSTAGE * G_STAGE) * sizeof(float);   // ~56.8 KB
    cudaFuncSetAttribute(gemm_tf32_kernel,
                         cudaFuncAttributeMaxDynamicSharedMemorySize, (int)gsmem);
    size_t asmem = (size_t)SMA_TOT * sizeof(float);                // ~174.6 KB
    cudaFuncSetAttribute(attn_tf32_kernel,
                         cudaFuncAttributeMaxDynamicSharedMemorySize, (int)asmem);

    // QKV projections (tf32 tensor cores, cp.async pipelined)
    gemm_tf32_kernel<<<dim3(D_ / GBN, MS_ / GBM), tb, gsmem>>>(X, Wq, bq, Qb, MS_, D_, D_);
    gemm_tf32_kernel<<<dim3(KV_ / GBN, MS_ / GBM), tb, gsmem>>>(X, Wk, bk, Kb, MS_, KV_, D_);
    gemm_tf32_kernel<<<dim3(KV_ / GBN, MS_ / GBM), tb, gsmem>>>(X, Wv, bv, Vb, MS_, KV_, D_);

    // attention
    attn_tf32_kernel<<<dim3(S_ / QT, B_ * H_), tb, asmem>>>(Qb, Kb, Vb, pad, Ob);

    // output projection
    gemm_tf32_kernel<<<dim3(D_ / GBN, MS_ / GBM), tb, gsmem>>>(Ob, Wo, bo, out, MS_, D_, D_);
}

// round 8
// speedup vs baseline: 10.7755x; 1.1585x over previous
#include <cuda_runtime.h>
#include <cuda_bf16.h>
#include <math.h>

// Problem constants
#define B_  2
#define S_  2048
#define D_  2048
#define H_  16
#define G_  4
#define DH_ 128
#define KV_ 512
#define MS_ (B_ * S_)

// -------------------- scratch (device globals; no allocs allowed) ----------
__device__ float g_Q[MS_ * D_];     // tf32 bits
__device__ float g_K[MS_ * KV_];    // tf32 bits
__device__ float g_V[MS_ * KV_];    // tf32 bits
__device__ float g_O[MS_ * D_];     // tf32 bits (attn out)
__device__ float g_X[MS_ * D_];     // tf32 bits of hidden_state
__device__ float g_Wq[D_ * D_];     // tf32 bits
__device__ float g_Wk[D_ * KV_];
__device__ float g_Wv[D_ * KV_];
__device__ float g_Wo[D_ * D_];

// -------------------- helpers ----------------------------------------------
__device__ __forceinline__ unsigned f2tf(float x) {
    unsigned u;
    asm("cvt.rna.tf32.f32 %0, %1;" : "=r"(u) : "f"(x));
    return u;
}

__device__ __forceinline__ void mma_tf32(float c[4], const unsigned a[4],
                                         unsigned b0, unsigned b1) {
    asm volatile(
        "mma.sync.aligned.m16n8k8.row.col.f32.tf32.tf32.f32 "
        "{%0,%1,%2,%3},{%4,%5,%6,%7},{%8,%9},{%0,%1,%2,%3};"
        : "+f"(c[0]), "+f"(c[1]), "+f"(c[2]), "+f"(c[3])
        : "r"(a[0]), "r"(a[1]), "r"(a[2]), "r"(a[3]), "r"(b0), "r"(b1));
}

__device__ __forceinline__ void cp16(void* sdst, const void* gsrc) {
    unsigned sa = (unsigned)__cvta_generic_to_shared(sdst);
    asm volatile("cp.async.cg.shared.global [%0], [%1], 16;" :: "r"(sa), "l"(gsrc));
}
#define CP_COMMIT() asm volatile("cp.async.commit_group;")
template<int N> __device__ __forceinline__ void cp_wait() {
    asm volatile("cp.async.wait_group %0;" :: "n"(N));
}

// ------------------- pre-pass: fp32 -> tf32 bits (stored as float) ---------
__global__ __launch_bounds__(256)
void cvt_tf32_kernel(const float4* __restrict__ src, float4* __restrict__ dst, int n4)
{
    int i = blockIdx.x * 256 + threadIdx.x;
    if (i >= n4) return;
    float4 v = src[i];
    float4 o;
    o.x = __uint_as_float(f2tf(v.x));
    o.y = __uint_as_float(f2tf(v.y));
    o.z = __uint_as_float(f2tf(v.z));
    o.w = __uint_as_float(f2tf(v.w));
    dst[i] = o;
}

// ======================= TF32 GEMM: C = A[M,K] @ W[K,N] + bias =============
// Inputs A, W hold tf32 bits. 128x128 tile, BK=16, 256 threads, warp 32x64.
// 3-stage cp.async pipeline; inner loop is pure LDS + MMA.
#define GBM 128
#define GBN 128
#define GBK 16
#define GA_STRIDE 20     // 16 + 4 pad  (A stored [m][k]); 20%32=20 -> r-pattern OK
#define GB_STRIDE 136    // 128 + 8 pad (B stored [k][n]); 136%32=8 -> tg-pattern OK
#define G_STAGE (GBM * GA_STRIDE + GBK * GB_STRIDE)
#define G_NSTAGE 3

__global__ __launch_bounds__(256)
void gemm_tf32_kernel(const float* __restrict__ A, const float* __restrict__ W,
                      const float* __restrict__ bias, float* __restrict__ C,
                      int M, int N, int K, int cvt_out)
{
    extern __shared__ float gsm[];

    const int tid  = threadIdx.x;
    const int w    = tid >> 5;
    const int lane = tid & 31;
    const int r    = lane >> 2;
    const int tg   = lane & 3;
    const int wm   = (w >> 1) * 32;
    const int wn   = (w & 1) * 64;

    const int bm = blockIdx.y * GBM;
    const int bn = blockIdx.x * GBN;

    const int aRow = tid >> 1;
    const int aCol = (tid & 1) * 8;
    const int bRow = tid >> 4;
    const int bCol = (tid & 15) * 8;

    const float* Ap = A + (size_t)(bm + aRow) * K + aCol;
    const float* Bp = W + (size_t)bRow * N + bn + bCol;

    float acc[2][8][4];
#pragma unroll
    for (int mt = 0; mt < 2; mt++)
#pragma unroll
        for (int nt = 0; nt < 8; nt++)
#pragma unroll
            for (int j = 0; j < 4; j++) acc[mt][nt][j] = 0.0f;

    auto issue = [&](int stage, int k0) {
        float* As = gsm + stage * G_STAGE;
        float* Bs = As + GBM * GA_STRIDE;
        cp16(&As[aRow * GA_STRIDE + aCol],     Ap + k0);
        cp16(&As[aRow * GA_STRIDE + aCol + 4], Ap + k0 + 4);
        cp16(&Bs[bRow * GB_STRIDE + bCol],     Bp + (size_t)k0 * N);
        cp16(&Bs[bRow * GB_STRIDE + bCol + 4], Bp + (size_t)k0 * N + 4);
    };

    issue(0, 0);       CP_COMMIT();
    issue(1, GBK);     CP_COMMIT();

    int stage = 0;
    for (int k0 = 0; k0 < K; k0 += GBK) {
        cp_wait<1>();
        __syncthreads();

        int knext = k0 + 2 * GBK;
        if (knext < K) {
            int ws = stage + 2; if (ws >= G_NSTAGE) ws -= G_NSTAGE;
            issue(ws, knext);
        }
        CP_COMMIT();

        const float* As = gsm + stage * G_STAGE;
        const float* Bs = As + GBM * GA_STRIDE;
#pragma unroll
        for (int ks = 0; ks < 2; ks++) {
            const int k = ks * 8;
            unsigned afr[2][4];
#pragma unroll
            for (int mt = 0; mt < 2; mt++) {
                const int m0 = wm + mt * 16;
                afr[mt][0] = __float_as_uint(As[(m0 + r) * GA_STRIDE + k + tg]);
                afr[mt][1] = __float_as_uint(As[(m0 + r + 8) * GA_STRIDE + k + tg]);
                afr[mt][2] = __float_as_uint(As[(m0 + r) * GA_STRIDE + k + tg + 4]);
                afr[mt][3] = __float_as_uint(As[(m0 + r + 8) * GA_STRIDE + k + tg + 4]);
            }
#pragma unroll
            for (int nt = 0; nt < 8; nt++) {
                const int n0 = wn + nt * 8;
                unsigned b0 = __float_as_uint(Bs[(k + tg) * GB_STRIDE + n0 + r]);
                unsigned b1 = __float_as_uint(Bs[(k + tg + 4) * GB_STRIDE + n0 + r]);
                mma_tf32(acc[0][nt], afr[0], b0, b1);
                mma_tf32(acc[1][nt], afr[1], b0, b1);
            }
        }
        stage++; if (stage >= G_NSTAGE) stage = 0;
    }

    // epilogue: add bias; optionally round to tf32 bits for downstream MMA use
#pragma unroll
    for (int mt = 0; mt < 2; mt++) {
        const int row0 = bm + wm + mt * 16 + r;
#pragma unroll
        for (int nt = 0; nt < 8; nt++) {
            const int col = bn + wn + nt * 8 + 2 * tg;
            float o0 = acc[mt][nt][0] + bias[col];
            float o1 = acc[mt][nt][1] + bias[col + 1];
            float o2 = acc[mt][nt][2] + bias[col];
            float o3 = acc[mt][nt][3] + bias[col + 1];
            if (cvt_out) {
                o0 = __uint_as_float(f2tf(o0)); o1 = __uint_as_float(f2tf(o1));
                o2 = __uint_as_float(f2tf(o2)); o3 = __uint_as_float(f2tf(o3));
            }
            float2 v0 = {o0, o1};
            float2 v1 = {o2, o3};
            *(float2*)&C[(size_t)row0 * N + col] = v0;
            *(float2*)&C[(size_t)(row0 + 8) * N + col] = v1;
        }
    }
}

// ======================= TF32 Flash attention (causal, GQA) ================
// Q/K/V hold tf32 bits. Block: 128 queries x one (b,h). 8 warps x 16 q-rows.
// cp.async double-buffered K/V tiles; inner loops pure LDS + MMA.
#define QT 128
#define KT 64
#define KSS 132      // K smem stride: 132%32=4  -> conflict-free for r-indexed rows
#define VSS 136      // V smem stride: 136%32=8  -> conflict-free for tg-indexed rows
#define PS_STRIDE 68

#define SMA_K 0
#define SMA_V (SMA_K + 2 * KT * KSS)
#define SMA_P (SMA_V + 2 * KT * VSS)
#define SMA_M (SMA_P + QT * PS_STRIDE)
#define SMA_TOT (SMA_M + 2 * KT)

__global__ __launch_bounds__(256)
void attn_tf32_kernel(const float* __restrict__ Q, const float* __restrict__ K,
                      const float* __restrict__ V, const float* __restrict__ pad,
                      float* __restrict__ O)
{
    extern __shared__ float asm_f[];
    float*    Ksf = asm_f + SMA_K;
    float*    Vsf = asm_f + SMA_V;
    unsigned* Ps  = (unsigned*)(asm_f + SMA_P);
    float*    Pmf = asm_f + SMA_M;

    const int tid  = threadIdx.x;
    const int w    = tid >> 5;
    const int lane = tid & 31;
    const int r    = lane >> 2;
    const int tg   = lane & 3;
    const int q0   = w * 16;

    const int bh = blockIdx.y;
    const int b  = bh >> 4;
    const int h  = bh & 15;
    const int g  = h >> 2;
    const int qb = gridDim.x - 1 - blockIdx.x;   // longest blocks first

    const int qg0 = qb * QT + q0 + r;
    const int qg1 = qg0 + 8;

    const float scale = 0.08838834764831845f;    // 1/sqrt(128), folded into Q

    const float* Kbase = K + (size_t)b * S_ * KV_ + g * DH_;
    const float* Vbase = V + (size_t)b * S_ * KV_ + g * DH_;

    auto issue_kv = [&](int buf, int krow0) {
        float* Kd = Ksf + buf * KT * KSS;
        float* Vd = Vsf + buf * KT * VSS;
#pragma unroll
        for (int it = 0; it < 8; it++) {
            int f = it * 256 + tid;
            int row = f >> 5;
            int c4 = (f & 31) * 4;
            cp16(&Kd[row * KSS + c4], Kbase + (size_t)(krow0 + row) * KV_ + c4);
            cp16(&Vd[row * VSS + c4], Vbase + (size_t)(krow0 + row) * KV_ + c4);
        }
        if (tid < 16)
            cp16(&Pmf[buf * KT + tid * 4], pad + b * S_ + krow0 + tid * 4);
    };

    const int ntiles = 2 * qb + 2;  // causal

    issue_kv(0, 0);
    CP_COMMIT();

    // ---- stage Q (tf32 bits) * scale -> re-round -> fragments in regs ----
    unsigned qf[16][4];
#pragma unroll
    for (int half = 0; half < 2; half++) {
#pragma unroll
        for (int it = 0; it < 8; it++) {
            int f = it * 256 + tid;
            int row = f >> 4;
            int c4 = (f & 15) * 4;
            float4 v = *(const float4*)(Q + (size_t)(b * S_ + qb * QT + row) * D_
                                          + h * DH_ + half * 64 + c4);
            uint4 u = {f2tf(v.x * scale), f2tf(v.y * scale),
                       f2tf(v.z * scale), f2tf(v.w * scale)};
            *(uint4*)&Ps[row * PS_STRIDE + c4] = u;
        }
        __syncthreads();
#pragma unroll
        for (int ks = 0; ks < 8; ks++) {
            int kk = half * 8 + ks;
            qf[kk][0] = Ps[(q0 + r) * PS_STRIDE + ks * 8 + tg];
            qf[kk][1] = Ps[(q0 + r + 8) * PS_STRIDE + ks * 8 + tg];
            qf[kk][2] = Ps[(q0 + r) * PS_STRIDE + ks * 8 + tg + 4];
            qf[kk][3] = Ps[(q0 + r + 8) * PS_STRIDE + ks * 8 + tg + 4];
        }
        __syncthreads();
    }

    float oacc[16][4];
#pragma unroll
    for (int nt = 0; nt < 16; nt++)
#pragma unroll
        for (int j = 0; j < 4; j++) oacc[nt][j] = 0.0f;
    float m0 = -1e30f, m1 = -1e30f, l0 = 0.0f, l1 = 0.0f;

    for (int kt = 0; kt < ntiles; kt++) {
        const int buf   = kt & 1;
        const int krow0 = kt * KT;

        cp_wait<0>();
        __syncthreads();

        if (kt + 1 < ntiles) issue_kv(buf ^ 1, krow0 + KT);
        CP_COMMIT();

        const float* Kt = Ksf + buf * KT * KSS;
        const float* Vt = Vsf + buf * KT * VSS;
        const float* Pm = Pmf + buf * KT;

        // ---- S = (Q*scale) K^T : pure LDS + MMA ----
        float sacc[8][4];
#pragma unroll
        for (int nt = 0; nt < 8; nt++)
#pragma unroll
            for (int j = 0; j < 4; j++) sacc[nt][j] = 0.0f;

#pragma unroll
        for (int ks = 0; ks < 16; ks++) {
#pragma unroll
            for (int nt = 0; nt < 8; nt++) {
                unsigned b0 = __float_as_uint(Kt[(nt * 8 + r) * KSS + ks * 8 + tg]);
                unsigned b1 = __float_as_uint(Kt[(nt * 8 + r) * KSS + ks * 8 + tg + 4]);
                mma_tf32(sacc[nt], qf[ks], b0, b1);
            }
        }

        // ---- mask ----
#pragma unroll
        for (int nt = 0; nt < 8; nt++) {
#pragma unroll
            for (int j = 0; j < 4; j++) {
                int col = nt * 8 + 2 * tg + (j & 1);
                int rowg = (j < 2) ? qg0 : qg1;
                int kg = krow0 + col;
                float s = sacc[nt][j] + Pm[col] * (-1e9f);
                if (kg > rowg) s = -1e30f;
                sacc[nt][j] = s;
            }
        }

        // ---- online softmax ----
        float tm0 = -1e30f, tm1 = -1e30f;
#pragma unroll
        for (int nt = 0; nt < 8; nt++) {
            tm0 = fmaxf(tm0, fmaxf(sacc[nt][0], sacc[nt][1]));
            tm1 = fmaxf(tm1, fmaxf(sacc[nt][2], sacc[nt][3]));
        }
        tm0 = fmaxf(tm0, __shfl_xor_sync(0xffffffffu, tm0, 1));
        tm0 = fmaxf(tm0, __shfl_xor_sync(0xffffffffu, tm0, 2));
        tm1 = fmaxf(tm1, __shfl_xor_sync(0xffffffffu, tm1, 1));
        tm1 = fmaxf(tm1, __shfl_xor_sync(0xffffffffu, tm1, 2));

        float mn0 = fmaxf(m0, tm0), mn1 = fmaxf(m1, tm1);
        float f0 = __expf(m0 - mn0), f1 = __expf(m1 - mn1);
        m0 = mn0; m1 = mn1;
        l0 *= f0; l1 *= f1;
#pragma unroll
        for (int nt = 0; nt < 16; nt++) {
            oacc[nt][0] *= f0; oacc[nt][1] *= f0;
            oacc[nt][2] *= f1; oacc[nt][3] *= f1;
        }

        float ps0 = 0.0f, ps1 = 0.0f;
#pragma unroll
        for (int nt = 0; nt < 8; nt++) {
            int col = nt * 8 + 2 * tg;
            float p0 = __expf(sacc[nt][0] - m0);
            float p1 = __expf(sacc[nt][1] - m0);
            float p2 = __expf(sacc[nt][2] - m1);
            float p3 = __expf(sacc[nt][3] - m1);
            ps0 += p0 + p1; ps1 += p2 + p3;
            Ps[(q0 + r) * PS_STRIDE + col]         = f2tf(p0);
            Ps[(q0 + r) * PS_STRIDE + col + 1]     = f2tf(p1);
            Ps[(q0 + r + 8) * PS_STRIDE + col]     = f2tf(p2);
            Ps[(q0 + r + 8) * PS_STRIDE + col + 1] = f2tf(p3);
        }
        ps0 += __shfl_xor_sync(0xffffffffu, ps0, 1);
        ps0 += __shfl_xor_sync(0xffffffffu, ps0, 2);
        ps1 += __shfl_xor_sync(0xffffffffu, ps1, 1);
        ps1 += __shfl_xor_sync(0xffffffffu, ps1, 2);
        l0 += ps0; l1 += ps1;
        __syncwarp();   // P rows are warp-private

        // ---- O += P V : pure LDS + MMA ----
#pragma unroll
        for (int ks = 0; ks < 8; ks++) {
            unsigned a[4];
            a[0] = Ps[(q0 + r) * PS_STRIDE + ks * 8 + tg];
            a[1] = Ps[(q0 + r + 8) * PS_STRIDE + ks * 8 + tg];
            a[2] = Ps[(q0 + r) * PS_STRIDE + ks * 8 + tg + 4];
            a[3] = Ps[(q0 + r + 8) * PS_STRIDE + ks * 8 + tg + 4];
#pragma unroll
            for (int nt = 0; nt < 16; nt++) {
                unsigned b0 = __float_as_uint(Vt[(ks * 8 + tg) * VSS + nt * 8 + r]);
                unsigned b1 = __float_as_uint(Vt[(ks * 8 + tg + 4) * VSS + nt * 8 + r]);
                mma_tf32(oacc[nt], a, b0, b1);
            }
        }
        // next iteration's top __syncthreads covers buffer reuse
    }

    // ---- epilogue: O/l, rounded to tf32 bits for the O-projection ----
    const float inv0 = 1.0f / l0, inv1 = 1.0f / l1;
    float* op0 = O + (size_t)(b * S_ + qg0) * D_ + h * DH_;
    float* op1 = O + (size_t)(b * S_ + qg1) * D_ + h * DH_;
#pragma unroll
    for (int nt = 0; nt < 16; nt++) {
        int col = nt * 8 + 2 * tg;
        float2 v0 = {__uint_as_float(f2tf(oacc[nt][0] * inv0)),
                     __uint_as_float(f2tf(oacc[nt][1] * inv0))};
        float2 v1 = {__uint_as_float(f2tf(oacc[nt][2] * inv1)),
                     __uint_as_float(f2tf(oacc[nt][3] * inv1))};
        *(float2*)(op0 + col) = v0;
        *(float2*)(op1 + col) = v1;
    }
}

// ============================== launch =====================================
extern "C" void kernel_launch(void* const* d_in, const int* in_sizes, int n_in,
                              void* d_out, int out_size)
{
    const float* X   = (const float*)d_in[0];
    // d_in[1] = causal mask (applied analytically)
    const float* pad = (const float*)d_in[2];
    const float* Wq  = (const float*)d_in[3];
    const float* bq  = (const float*)d_in[4];
    const float* Wk  = (const float*)d_in[5];
    const float* bk  = (const float*)d_in[6];
    const float* Wv  = (const float*)d_in[7];
    const float* bv  = (const float*)d_in[8];
    const float* Wo  = (const float*)d_in[9];
    const float* bo  = (const float*)d_in[10];
    float* out = (float*)d_out;

    float *Qb, *Kb, *Vb, *Ob, *Xb, *Wqb, *Wkb, *Wvb, *Wob;
    cudaGetSymbolAddress((void**)&Qb, g_Q);
    cudaGetSymbolAddress((void**)&Kb, g_K);
    cudaGetSymbolAddress((void**)&Vb, g_V);
    cudaGetSymbolAddress((void**)&Ob, g_O);
    cudaGetSymbolAddress((void**)&Xb, g_X);
    cudaGetSymbolAddress((void**)&Wqb, g_Wq);
    cudaGetSymbolAddress((void**)&Wkb, g_Wk);
    cudaGetSymbolAddress((void**)&Wvb, g_Wv);
    cudaGetSymbolAddress((void**)&Wob, g_Wo);

    dim3 tb(256);

    size_t gsmem = (size_t)(G_NSTAGE * G_STAGE) * sizeof(float);
    cudaFuncSetAttribute(gemm_tf32_kernel,
                         cudaFuncAttributeMaxDynamicSharedMemorySize, (int)gsmem);
    size_t asmem = (size_t)SMA_TOT * sizeof(float);
    cudaFuncSetAttribute(attn_tf32_kernel,
                         cudaFuncAttributeMaxDynamicSharedMemorySize, (int)asmem);

    // pre-pass: convert X and weights to tf32 bits (bandwidth-bound, ~25us)
    cvt_tf32_kernel<<<(MS_ * D_ / 4 + 255) / 256, tb>>>((const float4*)X,  (float4*)Xb,  MS_ * D_ / 4);
    cvt_tf32_kernel<<<(D_ * D_ / 4 + 255) / 256, tb>>>((const float4*)Wq, (float4*)Wqb, D_ * D_ / 4);
    cvt_tf32_kernel<<<(D_ * KV_ / 4 + 255) / 256, tb>>>((const float4*)Wk, (float4*)Wkb, D_ * KV_ / 4);
    cvt_tf32_kernel<<<(D_ * KV_ / 4 + 255) / 256, tb>>>((const float4*)Wv, (float4*)Wvb, D_ * KV_ / 4);
    cvt_tf32_kernel<<<(D_ * D_ / 4 + 255) / 256, tb>>>((const float4*)Wo, (float4*)Wob, D_ * D_ / 4);

    // QKV projections (tf32-bit outputs for the attention MMAs)
    gemm_tf32_kernel<<<dim3(D_ / GBN, MS_ / GBM), tb, gsmem>>>(Xb, Wqb, bq, Qb, MS_, D_, D_, 1);
    gemm_tf32_kernel<<<dim3(KV_ / GBN, MS_ / GBM), tb, gsmem>>>(Xb, Wkb, bk, Kb, MS_, KV_, D_, 1);
    gemm_tf32_kernel<<<dim3(KV_ / GBN, MS_ / GBM), tb, gsmem>>>(Xb, Wvb, bv, Vb, MS_, KV_, D_, 1);

    // attention
    attn_tf32_kernel<<<dim3(S_ / QT, B_ * H_), tb, asmem>>>(Qb, Kb, Vb, pad, Ob);

    // output projection (fp32 result)
    gemm_tf32_kernel<<<dim3(D_ / GBN, MS_ / GBM), tb, gsmem>>>(Ob, Wob, bo, out, MS_, D_, D_, 0);
}

// round 9
// speedup vs baseline: 10.9062x; 1.0121x over previous
#include <cuda_runtime.h>
#include <cuda_bf16.h>
#include <math.h>

// Problem constants
#define B_  2
#define S_  2048
#define D_  2048
#define H_  16
#define G_  4
#define DH_ 128
#define KV_ 512
#define MS_ (B_ * S_)

// -------------------- scratch (device globals; no allocs allowed) ----------
__device__ float g_Q[MS_ * D_];     // tf32 bits
__device__ float g_K[MS_ * KV_];    // tf32 bits
__device__ float g_V[MS_ * KV_];    // tf32 bits
__device__ float g_O[MS_ * D_];     // tf32 bits (attn out)
__device__ float g_X[MS_ * D_];     // tf32 bits of hidden_state
__device__ float g_Wq[D_ * D_];     // tf32 bits
__device__ float g_Wk[D_ * KV_];
__device__ float g_Wv[D_ * KV_];
__device__ float g_Wo[D_ * D_];

// -------------------- helpers ----------------------------------------------
__device__ __forceinline__ unsigned f2tf(float x) {
    unsigned u;
    asm("cvt.rna.tf32.f32 %0, %1;" : "=r"(u) : "f"(x));
    return u;
}

__device__ __forceinline__ void mma_tf32(float c[4], const unsigned a[4],
                                         unsigned b0, unsigned b1) {
    asm volatile(
        "mma.sync.aligned.m16n8k8.row.col.f32.tf32.tf32.f32 "
        "{%0,%1,%2,%3},{%4,%5,%6,%7},{%8,%9},{%0,%1,%2,%3};"
        : "+f"(c[0]), "+f"(c[1]), "+f"(c[2]), "+f"(c[3])
        : "r"(a[0]), "r"(a[1]), "r"(a[2]), "r"(a[3]), "r"(b0), "r"(b1));
}

__device__ __forceinline__ void cp16(void* sdst, const void* gsrc) {
    unsigned sa = (unsigned)__cvta_generic_to_shared(sdst);
    asm volatile("cp.async.cg.shared.global [%0], [%1], 16;" :: "r"(sa), "l"(gsrc));
}
#define CP_COMMIT() asm volatile("cp.async.commit_group;")
template<int N> __device__ __forceinline__ void cp_wait() {
    asm volatile("cp.async.wait_group %0;" :: "n"(N));
}

// ------------------- pre-pass: fp32 -> tf32 bits (stored as float) ---------
__global__ __launch_bounds__(256)
void cvt_tf32_kernel(const float4* __restrict__ src, float4* __restrict__ dst, int n4)
{
    int i = blockIdx.x * 256 + threadIdx.x;
    if (i >= n4) return;
    float4 v = src[i];
    float4 o;
    o.x = __uint_as_float(f2tf(v.x));
    o.y = __uint_as_float(f2tf(v.y));
    o.z = __uint_as_float(f2tf(v.z));
    o.w = __uint_as_float(f2tf(v.w));
    dst[i] = o;
}

// ======================= TF32 GEMM: C = A[M,K] @ W[K,N] + bias =============
// Inputs A, W hold tf32 bits. 128x128 tile, BK=16, 256 threads, warp 32x64.
// 3-stage cp.async pipeline; inner loop is pure LDS + MMA.
// __launch_bounds__(256, 2): cap regs at 128 so 2 CTAs co-reside per SM
// (smem 56.8KB/CTA also fits 2) -> 16 warps/SM for latency hiding.
#define GBM 128
#define GBN 128
#define GBK 16
#define GA_STRIDE 20     // 16 + 4 pad  (A stored [m][k])
#define GB_STRIDE 136    // 128 + 8 pad (B stored [k][n])
#define G_STAGE (GBM * GA_STRIDE + GBK * GB_STRIDE)
#define G_NSTAGE 3

__global__ __launch_bounds__(256, 2)
void gemm_tf32_kernel(const float* __restrict__ A, const float* __restrict__ W,
                      const float* __restrict__ bias, float* __restrict__ C,
                      int M, int N, int K, int cvt_out)
{
    extern __shared__ float gsm[];

    const int tid  = threadIdx.x;
    const int w    = tid >> 5;
    const int lane = tid & 31;
    const int r    = lane >> 2;
    const int tg   = lane & 3;
    const int wm   = (w >> 1) * 32;
    const int wn   = (w & 1) * 64;

    const int bm = blockIdx.y * GBM;
    const int bn = blockIdx.x * GBN;

    const int aRow = tid >> 1;
    const int aCol = (tid & 1) * 8;
    const int bRow = tid >> 4;
    const int bCol = (tid & 15) * 8;

    const float* Ap = A + (size_t)(bm + aRow) * K + aCol;
    const float* Bp = W + (size_t)bRow * N + bn + bCol;

    float acc[2][8][4];
#pragma unroll
    for (int mt = 0; mt < 2; mt++)
#pragma unroll
        for (int nt = 0; nt < 8; nt++)
#pragma unroll
            for (int j = 0; j < 4; j++) acc[mt][nt][j] = 0.0f;

    auto issue = [&](int stage, int k0) {
        float* As = gsm + stage * G_STAGE;
        float* Bs = As + GBM * GA_STRIDE;
        cp16(&As[aRow * GA_STRIDE + aCol],     Ap + k0);
        cp16(&As[aRow * GA_STRIDE + aCol + 4], Ap + k0 + 4);
        cp16(&Bs[bRow * GB_STRIDE + bCol],     Bp + (size_t)k0 * N);
        cp16(&Bs[bRow * GB_STRIDE + bCol + 4], Bp + (size_t)k0 * N + 4);
    };

    issue(0, 0);       CP_COMMIT();
    issue(1, GBK);     CP_COMMIT();

    int stage = 0;
    for (int k0 = 0; k0 < K; k0 += GBK) {
        cp_wait<1>();
        __syncthreads();

        int knext = k0 + 2 * GBK;
        if (knext < K) {
            int ws = stage + 2; if (ws >= G_NSTAGE) ws -= G_NSTAGE;
            issue(ws, knext);
        }
        CP_COMMIT();

        const float* As = gsm + stage * G_STAGE;
        const float* Bs = As + GBM * GA_STRIDE;
#pragma unroll
        for (int ks = 0; ks < 2; ks++) {
            const int k = ks * 8;
            unsigned afr[2][4];
#pragma unroll
            for (int mt = 0; mt < 2; mt++) {
                const int m0 = wm + mt * 16;
                afr[mt][0] = __float_as_uint(As[(m0 + r) * GA_STRIDE + k + tg]);
                afr[mt][1] = __float_as_uint(As[(m0 + r + 8) * GA_STRIDE + k + tg]);
                afr[mt][2] = __float_as_uint(As[(m0 + r) * GA_STRIDE + k + tg + 4]);
                afr[mt][3] = __float_as_uint(As[(m0 + r + 8) * GA_STRIDE + k + tg + 4]);
            }
#pragma unroll
            for (int nt = 0; nt < 8; nt++) {
                const int n0 = wn + nt * 8;
                unsigned b0 = __float_as_uint(Bs[(k + tg) * GB_STRIDE + n0 + r]);
                unsigned b1 = __float_as_uint(Bs[(k + tg + 4) * GB_STRIDE + n0 + r]);
                mma_tf32(acc[0][nt], afr[0], b0, b1);
                mma_tf32(acc[1][nt], afr[1], b0, b1);
            }
        }
        stage++; if (stage >= G_NSTAGE) stage = 0;
    }

    // epilogue: add bias; optionally round to tf32 bits for downstream MMA use
#pragma unroll
    for (int mt = 0; mt < 2; mt++) {
        const int row0 = bm + wm + mt * 16 + r;
#pragma unroll
        for (int nt = 0; nt < 8; nt++) {
            const int col = bn + wn + nt * 8 + 2 * tg;
            float o0 = acc[mt][nt][0] + bias[col];
            float o1 = acc[mt][nt][1] + bias[col + 1];
            float o2 = acc[mt][nt][2] + bias[col];
            float o3 = acc[mt][nt][3] + bias[col + 1];
            if (cvt_out) {
                o0 = __uint_as_float(f2tf(o0)); o1 = __uint_as_float(f2tf(o1));
                o2 = __uint_as_float(f2tf(o2)); o3 = __uint_as_float(f2tf(o3));
            }
            float2 v0 = {o0, o1};
            float2 v1 = {o2, o3};
            *(float2*)&C[(size_t)row0 * N + col] = v0;
            *(float2*)&C[(size_t)(row0 + 8) * N + col] = v1;
        }
    }
}

// ======================= TF32 Flash attention (causal, GQA) ================
// Q/K/V hold tf32 bits. Block: 128 queries x one (b,h). 8 warps x 16 q-rows.
// cp.async double-buffered K/V tiles; inner loops pure LDS + MMA.
// Causal fast-path: only the last 2 key tiles intersect the diagonal; interior
// tiles skip the per-element causal compare entirely.
#define QT 128
#define KT 64
#define KSS 132      // K smem stride: 132%32=4  -> conflict-free for r-indexed rows
#define VSS 136      // V smem stride: 136%32=8  -> conflict-free for tg-indexed rows
#define PS_STRIDE 68

#define SMA_K 0
#define SMA_V (SMA_K + 2 * KT * KSS)
#define SMA_P (SMA_V + 2 * KT * VSS)
#define SMA_M (SMA_P + QT * PS_STRIDE)
#define SMA_TOT (SMA_M + 2 * KT)

__global__ __launch_bounds__(256)
void attn_tf32_kernel(const float* __restrict__ Q, const float* __restrict__ K,
                      const float* __restrict__ V, const float* __restrict__ pad,
                      float* __restrict__ O)
{
    extern __shared__ float asm_f[];
    float*    Ksf = asm_f + SMA_K;
    float*    Vsf = asm_f + SMA_V;
    unsigned* Ps  = (unsigned*)(asm_f + SMA_P);
    float*    Pmf = asm_f + SMA_M;

    const int tid  = threadIdx.x;
    const int w    = tid >> 5;
    const int lane = tid & 31;
    const int r    = lane >> 2;
    const int tg   = lane & 3;
    const int q0   = w * 16;

    const int bh = blockIdx.y;
    const int b  = bh >> 4;
    const int h  = bh & 15;
    const int g  = h >> 2;
    const int qb = gridDim.x - 1 - blockIdx.x;   // longest blocks first

    const int qg0 = qb * QT + q0 + r;
    const int qg1 = qg0 + 8;

    const float scale = 0.08838834764831845f;    // 1/sqrt(128), folded into Q

    const float* Kbase = K + (size_t)b * S_ * KV_ + g * DH_;
    const float* Vbase = V + (size_t)b * S_ * KV_ + g * DH_;

    auto issue_kv = [&](int buf, int krow0) {
        float* Kd = Ksf + buf * KT * KSS;
        float* Vd = Vsf + buf * KT * VSS;
#pragma unroll
        for (int it = 0; it < 8; it++) {
            int f = it * 256 + tid;
            int row = f >> 5;
            int c4 = (f & 31) * 4;
            cp16(&Kd[row * KSS + c4], Kbase + (size_t)(krow0 + row) * KV_ + c4);
            cp16(&Vd[row * VSS + c4], Vbase + (size_t)(krow0 + row) * KV_ + c4);
        }
        if (tid < 16)
            cp16(&Pmf[buf * KT + tid * 4], pad + b * S_ + krow0 + tid * 4);
    };

    const int ntiles = 2 * qb + 2;  // causal

    issue_kv(0, 0);
    CP_COMMIT();

    // ---- stage Q (tf32 bits) * scale -> re-round -> fragments in regs ----
    unsigned qf[16][4];
#pragma unroll
    for (int half = 0; half < 2; half++) {
#pragma unroll
        for (int it = 0; it < 8; it++) {
            int f = it * 256 + tid;
            int row = f >> 4;
            int c4 = (f & 15) * 4;
            float4 v = *(const float4*)(Q + (size_t)(b * S_ + qb * QT + row) * D_
                                          + h * DH_ + half * 64 + c4);
            uint4 u = {f2tf(v.x * scale), f2tf(v.y * scale),
                       f2tf(v.z * scale), f2tf(v.w * scale)};
            *(uint4*)&Ps[row * PS_STRIDE + c4] = u;
        }
        __syncthreads();
#pragma unroll
        for (int ks = 0; ks < 8; ks++) {
            int kk = half * 8 + ks;
            qf[kk][0] = Ps[(q0 + r) * PS_STRIDE + ks * 8 + tg];
            qf[kk][1] = Ps[(q0 + r + 8) * PS_STRIDE + ks * 8 + tg];
            qf[kk][2] = Ps[(q0 + r) * PS_STRIDE + ks * 8 + tg + 4];
            qf[kk][3] = Ps[(q0 + r + 8) * PS_STRIDE + ks * 8 + tg + 4];
        }
        __syncthreads();
    }

    float oacc[16][4];
#pragma unroll
    for (int nt = 0; nt < 16; nt++)
#pragma unroll
        for (int j = 0; j < 4; j++) oacc[nt][j] = 0.0f;
    float m0 = -1e30f, m1 = -1e30f, l0 = 0.0f, l1 = 0.0f;

    for (int kt = 0; kt < ntiles; kt++) {
        const int buf   = kt & 1;
        const int krow0 = kt * KT;
        // Tile fully visible iff its last key <= the block's first query row.
        const bool need_causal = (krow0 + KT - 1) > qb * QT;

        cp_wait<0>();
        __syncthreads();

        if (kt + 1 < ntiles) issue_kv(buf ^ 1, krow0 + KT);
        CP_COMMIT();

        const float* Kt = Ksf + buf * KT * KSS;
        const float* Vt = Vsf + buf * KT * VSS;
        const float* Pm = Pmf + buf * KT;

        // ---- S = (Q*scale) K^T : pure LDS + MMA ----
        float sacc[8][4];
#pragma unroll
        for (int nt = 0; nt < 8; nt++)
#pragma unroll
            for (int j = 0; j < 4; j++) sacc[nt][j] = 0.0f;

#pragma unroll
        for (int ks = 0; ks < 16; ks++) {
#pragma unroll
            for (int nt = 0; nt < 8; nt++) {
                unsigned b0 = __float_as_uint(Kt[(nt * 8 + r) * KSS + ks * 8 + tg]);
                unsigned b1 = __float_as_uint(Kt[(nt * 8 + r) * KSS + ks * 8 + tg + 4]);
                mma_tf32(sacc[nt], qf[ks], b0, b1);
            }
        }

        // ---- mask (padding always; causal only on diagonal tiles) ----
        if (need_causal) {
#pragma unroll
            for (int nt = 0; nt < 8; nt++) {
#pragma unroll
                for (int j = 0; j < 4; j++) {
                    int col = nt * 8 + 2 * tg + (j & 1);
                    int rowg = (j < 2) ? qg0 : qg1;
                    int kg = krow0 + col;
                    float s = sacc[nt][j] + Pm[col] * (-1e9f);
                    if (kg > rowg) s = -1e30f;
                    sacc[nt][j] = s;
                }
            }
        } else {
#pragma unroll
            for (int nt = 0; nt < 8; nt++) {
#pragma unroll
                for (int j = 0; j < 4; j++) {
                    int col = nt * 8 + 2 * tg + (j & 1);
                    sacc[nt][j] += Pm[col] * (-1e9f);
                }
            }
        }

        // ---- online softmax ----
        float tm0 = -1e30f, tm1 = -1e30f;
#pragma unroll
        for (int nt = 0; nt < 8; nt++) {
            tm0 = fmaxf(tm0, fmaxf(sacc[nt][0], sacc[nt][1]));
            tm1 = fmaxf(tm1, fmaxf(sacc[nt][2], sacc[nt][3]));
        }
        tm0 = fmaxf(tm0, __shfl_xor_sync(0xffffffffu, tm0, 1));
        tm0 = fmaxf(tm0, __shfl_xor_sync(0xffffffffu, tm0, 2));
        tm1 = fmaxf(tm1, __shfl_xor_sync(0xffffffffu, tm1, 1));
        tm1 = fmaxf(tm1, __shfl_xor_sync(0xffffffffu, tm1, 2));

        float mn0 = fmaxf(m0, tm0), mn1 = fmaxf(m1, tm1);
        float f0 = __expf(m0 - mn0), f1 = __expf(m1 - mn1);
        m0 = mn0; m1 = mn1;
        l0 *= f0; l1 *= f1;
#pragma unroll
        for (int nt = 0; nt < 16; nt++) {
            oacc[nt][0] *= f0; oacc[nt][1] *= f0;
            oacc[nt][2] *= f1; oacc[nt][3] *= f1;
        }

        float ps0 = 0.0f, ps1 = 0.0f;
#pragma unroll
        for (int nt = 0; nt < 8; nt++) {
            int col = nt * 8 + 2 * tg;
            float p0 = __expf(sacc[nt][0] - m0);
            float p1 = __expf(sacc[nt][1] - m0);
            float p2 = __expf(sacc[nt][2] - m1);
            float p3 = __expf(sacc[nt][3] - m1);
            ps0 += p0 + p1; ps1 += p2 + p3;
            Ps[(q0 + r) * PS_STRIDE + col]         = f2tf(p0);
            Ps[(q0 + r) * PS_STRIDE + col + 1]     = f2tf(p1);
            Ps[(q0 + r + 8) * PS_STRIDE + col]     = f2tf(p2);
            Ps[(q0 + r + 8) * PS_STRIDE + col + 1] = f2tf(p3);
        }
        ps0 += __shfl_xor_sync(0xffffffffu, ps0, 1);
        ps0 += __shfl_xor_sync(0xffffffffu, ps0, 2);
        ps1 += __shfl_xor_sync(0xffffffffu, ps1, 1);
        ps1 += __shfl_xor_sync(0xffffffffu, ps1, 2);
        l0 += ps0; l1 += ps1;
        __syncwarp();   // P rows are warp-private

        // ---- O += P V : pure LDS + MMA ----
#pragma unroll
        for (int ks = 0; ks < 8; ks++) {
            unsigned a[4];
            a[0] = Ps[(q0 + r) * PS_STRIDE + ks * 8 + tg];
            a[1] = Ps[(q0 + r + 8) * PS_STRIDE + ks * 8 + tg];
            a[2] = Ps[(q0 + r) * PS_STRIDE + ks * 8 + tg + 4];
            a[3] = Ps[(q0 + r + 8) * PS_STRIDE + ks * 8 + tg + 4];
#pragma unroll
            for (int nt = 0; nt < 16; nt++) {
                unsigned b0 = __float_as_uint(Vt[(ks * 8 + tg) * VSS + nt * 8 + r]);
                unsigned b1 = __float_as_uint(Vt[(ks * 8 + tg + 4) * VSS + nt * 8 + r]);
                mma_tf32(oacc[nt], a, b0, b1);
            }
        }
        // next iteration's top __syncthreads covers buffer reuse
    }

    // ---- epilogue: O/l, rounded to tf32 bits for the O-projection ----
    const float inv0 = 1.0f / l0, inv1 = 1.0f / l1;
    float* op0 = O + (size_t)(b * S_ + qg0) * D_ + h * DH_;
    float* op1 = O + (size_t)(b * S_ + qg1) * D_ + h * DH_;
#pragma unroll
    for (int nt = 0; nt < 16; nt++) {
        int col = nt * 8 + 2 * tg;
        float2 v0 = {__uint_as_float(f2tf(oacc[nt][0] * inv0)),
                     __uint_as_float(f2tf(oacc[nt][1] * inv0))};
        float2 v1 = {__uint_as_float(f2tf(oacc[nt][2] * inv1)),
                     __uint_as_float(f2tf(oacc[nt][3] * inv1))};
        *(float2*)(op0 + col) = v0;
        *(float2*)(op1 + col) = v1;
    }
}

// ============================== launch =====================================
extern "C" void kernel_launch(void* const* d_in, const int* in_sizes, int n_in,
                              void* d_out, int out_size)
{
    const float* X   = (const float*)d_in[0];
    // d_in[1] = causal mask (applied analytically)
    const float* pad = (const float*)d_in[2];
    const float* Wq  = (const float*)d_in[3];
    const float* bq  = (const float*)d_in[4];
    const float* Wk  = (const float*)d_in[5];
    const float* bk  = (const float*)d_in[6];
    const float* Wv  = (const float*)d_in[7];
    const float* bv  = (const float*)d_in[8];
    const float* Wo  = (const float*)d_in[9];
    const float* bo  = (const float*)d_in[10];
    float* out = (float*)d_out;

    float *Qb, *Kb, *Vb, *Ob, *Xb, *Wqb, *Wkb, *Wvb, *Wob;
    cudaGetSymbolAddress((void**)&Qb, g_Q);
    cudaGetSymbolAddress((void**)&Kb, g_K);
    cudaGetSymbolAddress((void**)&Vb, g_V);
    cudaGetSymbolAddress((void**)&Ob, g_O);
    cudaGetSymbolAddress((void**)&Xb, g_X);
    cudaGetSymbolAddress((void**)&Wqb, g_Wq);
    cudaGetSymbolAddress((void**)&Wkb, g_Wk);
    cudaGetSymbolAddress((void**)&Wvb, g_Wv);
    cudaGetSymbolAddress((void**)&Wob, g_Wo);

    dim3 tb(256);

    size_t gsmem = (size_t)(G_NSTAGE * G_STAGE) * sizeof(float);
    cudaFuncSetAttribute(gemm_tf32_kernel,
                         cudaFuncAttributeMaxDynamicSharedMemorySize, (int)gsmem);
    size_t asmem = (size_t)SMA_TOT * sizeof(float);
    cudaFuncSetAttribute(attn_tf32_kernel,
                         cudaFuncAttributeMaxDynamicSharedMemorySize, (int)asmem);

    // pre-pass: convert X and weights to tf32 bits (bandwidth-bound, ~25us)
    cvt_tf32_kernel<<<(MS_ * D_ / 4 + 255) / 256, tb>>>((const float4*)X,  (float4*)Xb,  MS_ * D_ / 4);
    cvt_tf32_kernel<<<(D_ * D_ / 4 + 255) / 256, tb>>>((const float4*)Wq, (float4*)Wqb, D_ * D_ / 4);
    cvt_tf32_kernel<<<(D_ * KV_ / 4 + 255) / 256, tb>>>((const float4*)Wk, (float4*)Wkb, D_ * KV_ / 4);
    cvt_tf32_kernel<<<(D_ * KV_ / 4 + 255) / 256, tb>>>((const float4*)Wv, (float4*)Wvb, D_ * KV_ / 4);
    cvt_tf32_kernel<<<(D_ * D_ / 4 + 255) / 256, tb>>>((const float4*)Wo, (float4*)Wob, D_ * D_ / 4);

    // QKV projections (tf32-bit outputs for the attention MMAs)
    gemm_tf32_kernel<<<dim3(D_ / GBN, MS_ / GBM), tb, gsmem>>>(Xb, Wqb, bq, Qb, MS_, D_, D_, 1);
    gemm_tf32_kernel<<<dim3(KV_ / GBN, MS_ / GBM), tb, gsmem>>>(Xb, Wkb, bk, Kb, MS_, KV_, D_, 1);
    gemm_tf32_kernel<<<dim3(KV_ / GBN, MS_ / GBM), tb, gsmem>>>(Xb, Wvb, bv, Vb, MS_, KV_, D_, 1);

    // attention
    attn_tf32_kernel<<<dim3(S_ / QT, B_ * H_), tb, asmem>>>(Qb, Kb, Vb, pad, Ob);

    // output projection (fp32 result)
    gemm_tf32_kernel<<<dim3(D_ / GBN, MS_ / GBM), tb, gsmem>>>(Ob, Wob, bo, out, MS_, D_, D_, 0);
}